// round 2
// baseline (speedup 1.0000x reference)
#include <cuda_runtime.h>
#include <math.h>

#define B_    32
#define N_    577
#define DIM_  768
#define NH_   12
#define HD_   64
#define MLP_  3072
#define MTOK  (B_*N_)          /* 18464 */
#define QKVD  (3*DIM_)         /* 2304 */
#define SCALE_ 0.125f          /* 64^-0.5 */

#define QT 32
#define KT 64
#define KVP 68
#define SCPAD 584
#define ATTN_SMEM ((QT*64 + KT*KVP + QT*SCPAD)*4)  /* 100352 bytes */

// ---------------- scratch (static device memory; no allocations) ----------------
__device__ float g_h   [(size_t)MTOK * DIM_];    // LN1 / LN2 output
__device__ float g_qkv [(size_t)MTOK * QKVD];    // qkv projections
__device__ float g_att [(size_t)MTOK * DIM_];    // attention output (bnhd)
__device__ float g_m   [(size_t)MTOK * MLP_];    // MLP hidden
__device__ float g_rpbf[(size_t)NH_ * N_ * N_];  // expanded rel-pos bias [h][n][m]

// ---------------- LayerNorm ----------------
__global__ void __launch_bounds__(256)
ln_kernel(const float* __restrict__ in, const float* __restrict__ g,
          const float* __restrict__ bta, float* __restrict__ out)
{
    __shared__ float red[16];
    __shared__ float s_stats[2];
    const int row = blockIdx.x;
    const int tid = threadIdx.x;
    const float* p = in + (size_t)row * DIM_;
    float v0 = p[tid], v1 = p[tid + 256], v2 = p[tid + 512];
    float s1 = v0 + v1 + v2;
    float s2 = v0*v0 + v1*v1 + v2*v2;
    #pragma unroll
    for (int o = 16; o > 0; o >>= 1) {
        s1 += __shfl_xor_sync(0xffffffffu, s1, o);
        s2 += __shfl_xor_sync(0xffffffffu, s2, o);
    }
    const int warp = tid >> 5, lane = tid & 31;
    if (lane == 0) { red[warp] = s1; red[warp + 8] = s2; }
    __syncthreads();
    if (tid == 0) {
        float t1 = 0.f, t2 = 0.f;
        #pragma unroll
        for (int w = 0; w < 8; w++) { t1 += red[w]; t2 += red[w + 8]; }
        float mean = t1 * (1.f / DIM_);
        float var  = t2 * (1.f / DIM_) - mean * mean;
        s_stats[0] = mean;
        s_stats[1] = rsqrtf(var + 1e-6f);
    }
    __syncthreads();
    const float mean = s_stats[0], inv = s_stats[1];
    float* o = out + (size_t)row * DIM_;
    o[tid]       = (v0 - mean) * inv * g[tid]       + bta[tid];
    o[tid + 256] = (v1 - mean) * inv * g[tid + 256] + bta[tid + 256];
    o[tid + 512] = (v2 - mean) * inv * g[tid + 512] + bta[tid + 512];
}

// ---------------- expand rel-pos bias: rpbf[h][n][m] = table[relidx[n,m], h] ----------------
__global__ void rpb_expand(const float* __restrict__ table, const int* __restrict__ relidx,
                           float* __restrict__ out)
{
    int t = blockIdx.x * 256 + threadIdx.x;
    const int total = NH_ * N_ * N_;
    if (t >= total) return;
    int h = t / (N_ * N_);
    int r = t - h * (N_ * N_);
    out[t] = table[relidx[r] * NH_ + h];
}

// ---------------- SGEMM NT: C[M,Nn] = A[M,K] @ B[Nn,K]^T (+ epilogue) ----------------
// EPI 0: +bias(optional)   1: qkv concat bias   2: gelu(v+bias)   3: res + v + bias
template<int EPI>
__global__ void __launch_bounds__(256)
gemm_nt_kernel(const float* __restrict__ A, const float* __restrict__ Bw,
               float* __restrict__ C, int M, int Nn, int K,
               const float* __restrict__ bias, const float* __restrict__ bias2,
               const float* __restrict__ res)
{
    __shared__ float As[8][132];
    __shared__ float Bs[8][132];
    const int tid = threadIdx.x;
    const int mBase = blockIdx.y * 128;
    const int nBase = blockIdx.x * 128;
    const int lr = tid >> 1;
    const int lk = (tid & 1) * 4;
    const int ty = tid >> 4;
    const int tx = tid & 15;

    const bool aval = (mBase + lr) < M;
    const float* Ap = A + (size_t)(mBase + lr) * K + lk;
    const float* Bp = Bw + (size_t)(nBase + lr) * K + lk;

    float acc[8][8];
    #pragma unroll
    for (int i = 0; i < 8; i++)
        #pragma unroll
        for (int j = 0; j < 8; j++) acc[i][j] = 0.f;

    float4 av = aval ? *(const float4*)Ap : make_float4(0.f, 0.f, 0.f, 0.f);
    float4 bv = *(const float4*)Bp;

    for (int k0 = 0; k0 < K; k0 += 8) {
        __syncthreads();
        As[lk + 0][lr] = av.x; As[lk + 1][lr] = av.y; As[lk + 2][lr] = av.z; As[lk + 3][lr] = av.w;
        Bs[lk + 0][lr] = bv.x; Bs[lk + 1][lr] = bv.y; Bs[lk + 2][lr] = bv.z; Bs[lk + 3][lr] = bv.w;
        __syncthreads();
        if (k0 + 8 < K) {
            Ap += 8; Bp += 8;
            av = aval ? *(const float4*)Ap : make_float4(0.f, 0.f, 0.f, 0.f);
            bv = *(const float4*)Bp;
        }
        #pragma unroll
        for (int kk = 0; kk < 8; kk++) {
            float a[8], b[8];
            *(float4*)&a[0] = *(const float4*)&As[kk][ty * 8];
            *(float4*)&a[4] = *(const float4*)&As[kk][ty * 8 + 4];
            *(float4*)&b[0] = *(const float4*)&Bs[kk][tx * 8];
            *(float4*)&b[4] = *(const float4*)&Bs[kk][tx * 8 + 4];
            #pragma unroll
            for (int i = 0; i < 8; i++)
                #pragma unroll
                for (int j = 0; j < 8; j++)
                    acc[i][j] = fmaf(a[i], b[j], acc[i][j]);
        }
    }

    #pragma unroll
    for (int i = 0; i < 8; i++) {
        int gm = mBase + ty * 8 + i;
        if (gm >= M) continue;
        size_t rowoff = (size_t)gm * Nn;
        #pragma unroll
        for (int j = 0; j < 8; j++) {
            int gn = nBase + tx * 8 + j;
            float v = acc[i][j];
            if (EPI == 0) {
                if (bias) v += bias[gn];
            } else if (EPI == 1) {
                v += (gn < 768) ? bias[gn] : ((gn < 1536) ? 0.f : bias2[gn - 1536]);
            } else if (EPI == 2) {
                v += bias[gn];
                v = 0.5f * v * (1.f + erff(v * 0.70710678118654752f));
            } else {
                v += bias[gn];
                v += res[rowoff + gn];
            }
            C[rowoff + gn] = v;
        }
    }
}

// ---------------- fused attention: per (b, h, 32-query tile) ----------------
__global__ void __launch_bounds__(256)
attn_kernel(const float* __restrict__ qkv, const float* __restrict__ rpbf,
            float* __restrict__ out)
{
    extern __shared__ float sm[];
    float* s_q  = sm;                     // QT*64
    float* s_kv = sm + QT * 64;           // KT*KVP
    float* s_sc = s_kv + KT * KVP;        // QT*SCPAD

    const int tid = threadIdx.x;
    const int q0 = blockIdx.x * QT;
    const int h  = blockIdx.y;
    const int b  = blockIdx.z;
    const size_t qkv_base = (size_t)b * N_ * QKVD;

    // load Q tile (pre-scaled)
    #pragma unroll
    for (int q = 0; q < 2; q++) {
        int idx4 = q * 256 + tid;        // 0..511 (float4 units)
        int row = idx4 >> 4;             // 0..31
        int c4  = idx4 & 15;
        int n = q0 + row;
        float4 v = make_float4(0.f, 0.f, 0.f, 0.f);
        if (n < N_) v = *(const float4*)(qkv + qkv_base + (size_t)n * QKVD + h * 64 + c4 * 4);
        v.x *= SCALE_; v.y *= SCALE_; v.z *= SCALE_; v.w *= SCALE_;
        *(float4*)&s_q[row * 64 + c4 * 4] = v;
    }

    const int qi = tid >> 3;
    const int kl = tid & 7;
    const int nrow = q0 + qi;
    const float* rpb_row = rpbf + ((size_t)h * N_ + (nrow < N_ ? nrow : 0)) * N_;

    // ---- scores: S = (Q*scale) K^T + rpb ----
    for (int c = 0; c < 10; c++) {
        __syncthreads();   // protect s_kv from previous iteration / s_q from load
        #pragma unroll
        for (int q = 0; q < 4; q++) {
            int idx4 = q * 256 + tid;    // 0..1023
            int row = idx4 >> 4;         // 0..63
            int c4 = idx4 & 15;
            int kk = c * 64 + row;
            float4 v = make_float4(0.f, 0.f, 0.f, 0.f);
            if (kk < N_) v = *(const float4*)(qkv + qkv_base + (size_t)kk * QKVD + 768 + h * 64 + c4 * 4);
            *(float4*)&s_kv[row * KVP + c4 * 4] = v;
        }
        __syncthreads();
        float acc[8] = {0.f, 0.f, 0.f, 0.f, 0.f, 0.f, 0.f, 0.f};
        #pragma unroll
        for (int d4 = 0; d4 < 16; d4++) {
            float4 qv = *(const float4*)&s_q[qi * 64 + d4 * 4];
            #pragma unroll
            for (int jj = 0; jj < 8; jj++) {
                float4 kv = *(const float4*)&s_kv[(kl + jj * 8) * KVP + d4 * 4];
                acc[jj] += qv.x * kv.x + qv.y * kv.y + qv.z * kv.z + qv.w * kv.w;
            }
        }
        #pragma unroll
        for (int jj = 0; jj < 8; jj++) {
            int mc = c * 64 + kl + jj * 8;
            if (mc < N_) {
                float bvv = (nrow < N_) ? rpb_row[mc] : 0.f;
                s_sc[qi * SCPAD + mc] = acc[jj] + bvv;
            }
        }
    }
    __syncthreads();

    // ---- softmax (one warp handles 4 rows) ----
    {
        const int warp = tid >> 5, lane = tid & 31;
        for (int row = warp; row < QT; row += 8) {
            float* sr = s_sc + row * SCPAD;
            float mx = -1e30f;
            for (int j = lane; j < N_; j += 32) mx = fmaxf(mx, sr[j]);
            #pragma unroll
            for (int o = 16; o > 0; o >>= 1) mx = fmaxf(mx, __shfl_xor_sync(0xffffffffu, mx, o));
            float sum = 0.f;
            for (int j = lane; j < N_; j += 32) { float e = __expf(sr[j] - mx); sr[j] = e; sum += e; }
            #pragma unroll
            for (int o = 16; o > 0; o >>= 1) sum += __shfl_xor_sync(0xffffffffu, sum, o);
            float inv = 1.f / sum;
            for (int j = lane; j < N_; j += 32) sr[j] *= inv;
        }
    }
    __syncthreads();

    // ---- O = P @ V ----
    const int d0 = (tid & 7) * 8;
    float4 o0 = make_float4(0.f, 0.f, 0.f, 0.f);
    float4 o1 = make_float4(0.f, 0.f, 0.f, 0.f);
    for (int c = 0; c < 10; c++) {
        __syncthreads();
        #pragma unroll
        for (int q = 0; q < 4; q++) {
            int idx4 = q * 256 + tid;
            int row = idx4 >> 4;
            int c4 = idx4 & 15;
            int kk = c * 64 + row;
            float4 v = make_float4(0.f, 0.f, 0.f, 0.f);
            if (kk < N_) v = *(const float4*)(qkv + qkv_base + (size_t)kk * QKVD + 1536 + h * 64 + c4 * 4);
            *(float4*)&s_kv[row * KVP + c4 * 4] = v;
        }
        __syncthreads();
        int rlim = min(64, N_ - c * 64);
        for (int r = 0; r < rlim; r++) {
            float p = s_sc[qi * SCPAD + c * 64 + r];
            float4 v0 = *(const float4*)&s_kv[r * KVP + d0];
            float4 v1 = *(const float4*)&s_kv[r * KVP + d0 + 4];
            o0.x = fmaf(p, v0.x, o0.x); o0.y = fmaf(p, v0.y, o0.y);
            o0.z = fmaf(p, v0.z, o0.z); o0.w = fmaf(p, v0.w, o0.w);
            o1.x = fmaf(p, v1.x, o1.x); o1.y = fmaf(p, v1.y, o1.y);
            o1.z = fmaf(p, v1.z, o1.z); o1.w = fmaf(p, v1.w, o1.w);
        }
    }
    if (nrow < N_) {
        float* op = out + ((size_t)b * N_ + nrow) * DIM_ + h * 64 + d0;
        *(float4*)op = o0;
        *(float4*)(op + 4) = o1;
    }
}

// ---------------- launch ----------------
extern "C" void kernel_launch(void* const* d_in, const int* in_sizes, int n_in,
                              void* d_out, int out_size)
{
    const float* x     = (const float*)d_in[0];
    const float* n1g   = (const float*)d_in[1];
    const float* n1b   = (const float*)d_in[2];
    const float* qkvw  = (const float*)d_in[3];
    const float* qb    = (const float*)d_in[4];
    const float* vb    = (const float*)d_in[5];
    const float* rpbt  = (const float*)d_in[6];
    const float* projw = (const float*)d_in[7];
    const float* projb = (const float*)d_in[8];
    const float* n2g   = (const float*)d_in[9];
    const float* n2b   = (const float*)d_in[10];
    const float* fc1w  = (const float*)d_in[11];
    const float* fc1b  = (const float*)d_in[12];
    const float* fc2w  = (const float*)d_in[13];
    const float* fc2b  = (const float*)d_in[14];
    const int*   ridx  = (const int*)d_in[15];
    float* out = (float*)d_out;

    float *ph, *pqkv, *patt, *pm, *prpb;
    cudaGetSymbolAddress((void**)&ph,   g_h);
    cudaGetSymbolAddress((void**)&pqkv, g_qkv);
    cudaGetSymbolAddress((void**)&patt, g_att);
    cudaGetSymbolAddress((void**)&pm,   g_m);
    cudaGetSymbolAddress((void**)&prpb, g_rpbf);

    cudaFuncSetAttribute(attn_kernel, cudaFuncAttributeMaxDynamicSharedMemorySize, ATTN_SMEM);

    const int mTiles = (MTOK + 127) / 128;

    // 1. h = LN1(x)
    ln_kernel<<<MTOK, 256>>>(x, n1g, n1b, ph);
    // 1b. expand rel-pos bias
    rpb_expand<<<(NH_ * N_ * N_ + 255) / 256, 256>>>(rpbt, ridx, prpb);
    // 2. qkv = h @ qkv_w^T + [q_bias, 0, v_bias]
    gemm_nt_kernel<1><<<dim3(QKVD / 128, mTiles), 256>>>(ph, qkvw, pqkv, MTOK, QKVD, DIM_, qb, vb, nullptr);
    // 3. fused attention
    attn_kernel<<<dim3((N_ + QT - 1) / QT, NH_, B_), 256, ATTN_SMEM>>>(pqkv, prpb, patt);
    // 4. x2 = x + att @ proj_w^T + proj_b   (into d_out)
    gemm_nt_kernel<3><<<dim3(DIM_ / 128, mTiles), 256>>>(patt, projw, out, MTOK, DIM_, DIM_, projb, nullptr, x);
    // 5. h2 = LN2(x2)
    ln_kernel<<<MTOK, 256>>>(out, n2g, n2b, ph);
    // 6. m = gelu(h2 @ fc1_w^T + fc1_b)
    gemm_nt_kernel<2><<<dim3(MLP_ / 128, mTiles), 256>>>(ph, fc1w, pm, MTOK, MLP_, DIM_, fc1b, nullptr, nullptr);
    // 7. out = x2 + m @ fc2_w^T + fc2_b   (in-place on d_out)
    gemm_nt_kernel<3><<<dim3(DIM_ / 128, mTiles), 256>>>(pm, fc2w, out, MTOK, DIM_, MLP_, fc2b, nullptr, out);
}

// round 3
// speedup vs baseline: 2.9487x; 2.9487x over previous
#include <cuda_runtime.h>
#include <math.h>

#define B_    32
#define N_    577
#define DIM_  768
#define NH_   12
#define HD_   64
#define MLP_  3072
#define MTOK  (B_*N_)          /* 18464 */
#define QKVD  (3*DIM_)         /* 2304 */
#define SCALE_ 0.125f

// attention smem strides (floats) — chosen for conflict-free mma fragment loads
#define SQ_STR 68
#define SK_STR 76
#define SV_STR 72
#define SC_STR 652
#define ATTN_SMEM ((32*SQ_STR + 64*SK_STR + 32*SC_STR + 32) * 4)

// ---------------- scratch ----------------
__device__ float g_h   [(size_t)MTOK * DIM_];
__device__ float g_qkv [(size_t)MTOK * QKVD];
__device__ float g_att [(size_t)MTOK * DIM_];
__device__ float g_m   [(size_t)MTOK * MLP_];
__device__ float g_rpbf[(size_t)NH_ * N_ * N_];

// ---------------- helpers ----------------
__device__ __forceinline__ unsigned f2tf(float f) {
    unsigned u; asm("cvt.rna.tf32.f32 %0, %1;" : "=r"(u) : "f"(f)); return u;
}
__device__ __forceinline__ void mma8(float* c, const unsigned* a, const unsigned* b) {
    asm volatile(
        "mma.sync.aligned.m16n8k8.row.col.f32.tf32.tf32.f32 "
        "{%0,%1,%2,%3},{%4,%5,%6,%7},{%8,%9},{%0,%1,%2,%3};"
        : "+f"(c[0]), "+f"(c[1]), "+f"(c[2]), "+f"(c[3])
        : "r"(a[0]), "r"(a[1]), "r"(a[2]), "r"(a[3]), "r"(b[0]), "r"(b[1]));
}

// ---------------- LayerNorm ----------------
__global__ void __launch_bounds__(256)
ln_kernel(const float* __restrict__ in, const float* __restrict__ g,
          const float* __restrict__ bta, float* __restrict__ out)
{
    __shared__ float red[16];
    __shared__ float s_stats[2];
    const int row = blockIdx.x;
    const int tid = threadIdx.x;
    const float* p = in + (size_t)row * DIM_;
    float v0 = p[tid], v1 = p[tid + 256], v2 = p[tid + 512];
    float s1 = v0 + v1 + v2;
    float s2 = v0*v0 + v1*v1 + v2*v2;
    #pragma unroll
    for (int o = 16; o > 0; o >>= 1) {
        s1 += __shfl_xor_sync(0xffffffffu, s1, o);
        s2 += __shfl_xor_sync(0xffffffffu, s2, o);
    }
    const int warp = tid >> 5, lane = tid & 31;
    if (lane == 0) { red[warp] = s1; red[warp + 8] = s2; }
    __syncthreads();
    if (tid == 0) {
        float t1 = 0.f, t2 = 0.f;
        #pragma unroll
        for (int w = 0; w < 8; w++) { t1 += red[w]; t2 += red[w + 8]; }
        float mean = t1 * (1.f / DIM_);
        float var  = t2 * (1.f / DIM_) - mean * mean;
        s_stats[0] = mean;
        s_stats[1] = rsqrtf(var + 1e-6f);
    }
    __syncthreads();
    const float mean = s_stats[0], inv = s_stats[1];
    float* o = out + (size_t)row * DIM_;
    o[tid]       = (v0 - mean) * inv * g[tid]       + bta[tid];
    o[tid + 256] = (v1 - mean) * inv * g[tid + 256] + bta[tid + 256];
    o[tid + 512] = (v2 - mean) * inv * g[tid + 512] + bta[tid + 512];
}

// ---------------- rel-pos bias expand ----------------
__global__ void rpb_expand(const float* __restrict__ table, const int* __restrict__ relidx,
                           float* __restrict__ out)
{
    int t = blockIdx.x * 256 + threadIdx.x;
    const int total = NH_ * N_ * N_;
    if (t >= total) return;
    int h = t / (N_ * N_);
    int r = t - h * (N_ * N_);
    out[t] = table[relidx[r] * NH_ + h];
}

// ---------------- TF32 tensor-core GEMM NT ----------------
// C[M,Nn] = A[M,K] @ Bw[Nn,K]^T + epilogue
// EPI 1: qkv concat bias   2: gelu(v+bias)   3: res + v + bias
template<int EPI>
__global__ void __launch_bounds__(256)
gemm_tc(const float* __restrict__ A, const float* __restrict__ Bw,
        float* __restrict__ C, int M, int Nn, int K,
        const float* __restrict__ bias, const float* __restrict__ bias2,
        const float* __restrict__ res)
{
    __shared__ unsigned As[128 * 20];
    __shared__ unsigned Bs[128 * 20];
    const int tid = threadIdx.x;
    const int warp = tid >> 5, lane = tid & 31;
    const int groupID = lane >> 2, tid4 = lane & 3;
    const int warpM = warp & 1, warpN = warp >> 1;
    const int mBase = blockIdx.y * 128;
    const int nBase = blockIdx.x * 128;

    // global load mapping: 64 rows per pass, 4 float4 per row
    const int lr  = tid >> 2;       // 0..63
    const int lc4 = tid & 3;        // 0..3

    const bool av0ok = (mBase + lr)      < M;
    const bool av1ok = (mBase + lr + 64) < M;
    const float* Ap0 = A  + (size_t)(mBase + lr)      * K + lc4 * 4;
    const float* Ap1 = A  + (size_t)(mBase + lr + 64) * K + lc4 * 4;
    const float* Bp0 = Bw + (size_t)(nBase + lr)      * K + lc4 * 4;
    const float* Bp1 = Bw + (size_t)(nBase + lr + 64) * K + lc4 * 4;

    float acc[4][4][4];
    #pragma unroll
    for (int i = 0; i < 4; i++)
        #pragma unroll
        for (int j = 0; j < 4; j++)
            #pragma unroll
            for (int r = 0; r < 4; r++) acc[i][j][r] = 0.f;

    const float4 zero4 = make_float4(0.f, 0.f, 0.f, 0.f);
    float4 a0 = av0ok ? *(const float4*)Ap0 : zero4;
    float4 a1 = av1ok ? *(const float4*)Ap1 : zero4;
    float4 b0 = *(const float4*)Bp0;
    float4 b1 = *(const float4*)Bp1;

    for (int k0 = 0; k0 < K; k0 += 16) {
        __syncthreads();
        {
            uint4 u;
            u.x = f2tf(a0.x); u.y = f2tf(a0.y); u.z = f2tf(a0.z); u.w = f2tf(a0.w);
            *(uint4*)&As[lr * 20 + lc4 * 4] = u;
            u.x = f2tf(a1.x); u.y = f2tf(a1.y); u.z = f2tf(a1.z); u.w = f2tf(a1.w);
            *(uint4*)&As[(lr + 64) * 20 + lc4 * 4] = u;
            u.x = f2tf(b0.x); u.y = f2tf(b0.y); u.z = f2tf(b0.z); u.w = f2tf(b0.w);
            *(uint4*)&Bs[lr * 20 + lc4 * 4] = u;
            u.x = f2tf(b1.x); u.y = f2tf(b1.y); u.z = f2tf(b1.z); u.w = f2tf(b1.w);
            *(uint4*)&Bs[(lr + 64) * 20 + lc4 * 4] = u;
        }
        __syncthreads();
        if (k0 + 16 < K) {
            Ap0 += 16; Ap1 += 16; Bp0 += 16; Bp1 += 16;
            a0 = av0ok ? *(const float4*)Ap0 : zero4;
            a1 = av1ok ? *(const float4*)Ap1 : zero4;
            b0 = *(const float4*)Bp0;
            b1 = *(const float4*)Bp1;
        }
        #pragma unroll
        for (int kg = 0; kg < 16; kg += 8) {
            unsigned afr[4][4], bfr[4][2];
            #pragma unroll
            for (int i = 0; i < 4; i++) {
                int r = warpM * 64 + i * 16 + groupID;
                afr[i][0] = As[r * 20 + kg + tid4];
                afr[i][1] = As[(r + 8) * 20 + kg + tid4];
                afr[i][2] = As[r * 20 + kg + tid4 + 4];
                afr[i][3] = As[(r + 8) * 20 + kg + tid4 + 4];
            }
            #pragma unroll
            for (int j = 0; j < 4; j++) {
                int cn = warpN * 32 + j * 8 + groupID;
                bfr[j][0] = Bs[cn * 20 + kg + tid4];
                bfr[j][1] = Bs[cn * 20 + kg + tid4 + 4];
            }
            #pragma unroll
            for (int i = 0; i < 4; i++)
                #pragma unroll
                for (int j = 0; j < 4; j++)
                    mma8(acc[i][j], afr[i], bfr[j]);
        }
    }

    // epilogue
    #pragma unroll
    for (int i = 0; i < 4; i++) {
        int r0 = mBase + warpM * 64 + i * 16 + groupID;
        int r1 = r0 + 8;
        #pragma unroll
        for (int j = 0; j < 4; j++) {
            int cn = nBase + warpN * 32 + j * 8 + tid4 * 2;
            float bv0, bv1;
            if (EPI == 1) {
                bv0 = (cn < 768) ? bias[cn] : ((cn < 1536) ? 0.f : bias2[cn - 1536]);
                int c1 = cn + 1;
                bv1 = (c1 < 768) ? bias[c1] : ((c1 < 1536) ? 0.f : bias2[c1 - 1536]);
            } else {
                bv0 = bias[cn]; bv1 = bias[cn + 1];
            }
            #pragma unroll
            for (int rr = 0; rr < 2; rr++) {
                int gm = rr ? r1 : r0;
                if (gm >= M) continue;
                size_t off = (size_t)gm * Nn + cn;
                float v0 = acc[i][j][rr * 2 + 0] + bv0;
                float v1 = acc[i][j][rr * 2 + 1] + bv1;
                if (EPI == 2) {
                    v0 = 0.5f * v0 * (1.f + erff(v0 * 0.70710678118654752f));
                    v1 = 0.5f * v1 * (1.f + erff(v1 * 0.70710678118654752f));
                } else if (EPI == 3) {
                    v0 += res[off]; v1 += res[off + 1];
                }
                float2 o; o.x = v0; o.y = v1;
                *(float2*)&C[off] = o;
            }
        }
    }
}

// ---------------- fused tensor-core attention ----------------
__global__ void __launch_bounds__(256)
attn_kernel(const float* __restrict__ qkv, const float* __restrict__ rpbf,
            float* __restrict__ out)
{
    extern __shared__ unsigned smu[];
    unsigned* s_q  = smu;                       // 32*68
    unsigned* s_kv = smu + 32 * SQ_STR;         // 64*76 (K) / 64*72 (V)
    float*    s_sc = (float*)(s_kv + 64 * SK_STR); // 32*652
    float*    s_inv = s_sc + 32 * SC_STR;       // 32

    const int tid = threadIdx.x;
    const int warp = tid >> 5, lane = tid & 31;
    const int groupID = lane >> 2, tid4 = lane & 3;
    const int warpM = warp & 1, warpN = warp >> 1;
    const int q0 = blockIdx.x * 32;
    const int h  = blockIdx.y;
    const int b  = blockIdx.z;
    const size_t qkv_base = (size_t)b * N_ * QKVD;
    const float4 zero4 = make_float4(0.f, 0.f, 0.f, 0.f);

    // load Q tile (pre-scaled, tf32)
    #pragma unroll
    for (int q = 0; q < 2; q++) {
        int idx4 = q * 256 + tid;
        int row = idx4 >> 4;
        int c4  = idx4 & 15;
        int n = q0 + row;
        float4 v = (n < N_) ? *(const float4*)(qkv + qkv_base + (size_t)n * QKVD + h * 64 + c4 * 4) : zero4;
        uint4 u;
        u.x = f2tf(v.x * SCALE_); u.y = f2tf(v.y * SCALE_);
        u.z = f2tf(v.z * SCALE_); u.w = f2tf(v.w * SCALE_);
        *(uint4*)&s_q[row * SQ_STR + c4 * 4] = u;
    }

    // ---- S = (Q*scale) K^T ----
    for (int c = 0; c < 10; c++) {
        __syncthreads();
        #pragma unroll
        for (int q = 0; q < 4; q++) {
            int idx4 = q * 256 + tid;
            int row = idx4 >> 4;
            int c4  = idx4 & 15;
            int kk = c * 64 + row;
            float4 v = (kk < N_) ? *(const float4*)(qkv + qkv_base + (size_t)kk * QKVD + 768 + h * 64 + c4 * 4) : zero4;
            uint4 u; u.x = f2tf(v.x); u.y = f2tf(v.y); u.z = f2tf(v.z); u.w = f2tf(v.w);
            *(uint4*)&s_kv[row * SK_STR + c4 * 4] = u;
        }
        __syncthreads();

        float sacc[2][4];
        #pragma unroll
        for (int j = 0; j < 2; j++)
            #pragma unroll
            for (int r = 0; r < 4; r++) sacc[j][r] = 0.f;
        const int qrow = warpM * 16 + groupID;
        #pragma unroll
        for (int kg = 0; kg < 8; kg++) {
            unsigned aq[4];
            aq[0] = s_q[qrow * SQ_STR + kg * 8 + tid4];
            aq[1] = s_q[(qrow + 8) * SQ_STR + kg * 8 + tid4];
            aq[2] = s_q[qrow * SQ_STR + kg * 8 + tid4 + 4];
            aq[3] = s_q[(qrow + 8) * SQ_STR + kg * 8 + tid4 + 4];
            #pragma unroll
            for (int j = 0; j < 2; j++) {
                int kcol = warpN * 16 + j * 8 + groupID;
                unsigned bk[2];
                bk[0] = s_kv[kcol * SK_STR + kg * 8 + tid4];
                bk[1] = s_kv[kcol * SK_STR + kg * 8 + tid4 + 4];
                mma8(sacc[j], aq, bk);
            }
        }
        #pragma unroll
        for (int j = 0; j < 2; j++) {
            int col = c * 64 + warpN * 16 + j * 8 + tid4 * 2;
            int r = warpM * 16 + groupID;
            s_sc[r * SC_STR + col]           = (col     < N_) ? sacc[j][0] : 0.f;
            s_sc[r * SC_STR + col + 1]       = (col + 1 < N_) ? sacc[j][1] : 0.f;
            s_sc[(r + 8) * SC_STR + col]     = (col     < N_) ? sacc[j][2] : 0.f;
            s_sc[(r + 8) * SC_STR + col + 1] = (col + 1 < N_) ? sacc[j][3] : 0.f;
        }
    }
    __syncthreads();

    // ---- softmax (+rpb); store unnormalized exp as tf32, keep 1/sum ----
    {
        for (int row = warp; row < 32; row += 8) {
            int nrow = q0 + row;
            const float* rb = rpbf + ((size_t)h * N_ + (nrow < N_ ? nrow : 0)) * N_;
            float* sr = s_sc + row * SC_STR;
            float mx = -1e30f;
            for (int j = lane; j < N_; j += 32) mx = fmaxf(mx, sr[j] + rb[j]);
            #pragma unroll
            for (int o = 16; o > 0; o >>= 1) mx = fmaxf(mx, __shfl_xor_sync(0xffffffffu, mx, o));
            float sum = 0.f;
            for (int j = lane; j < N_; j += 32) {
                float e = __expf(sr[j] + rb[j] - mx);
                sr[j] = __uint_as_float(f2tf(e));
                sum += e;
            }
            #pragma unroll
            for (int o = 16; o > 0; o >>= 1) sum += __shfl_xor_sync(0xffffffffu, sum, o);
            if (lane == 0) s_inv[row] = 1.f / sum;
        }
    }

    // ---- O = P @ V ----
    float oacc[2][4];
    #pragma unroll
    for (int j = 0; j < 2; j++)
        #pragma unroll
        for (int r = 0; r < 4; r++) oacc[j][r] = 0.f;

    const unsigned* s_scu = (const unsigned*)s_sc;
    for (int c = 0; c < 10; c++) {
        __syncthreads();
        #pragma unroll
        for (int q = 0; q < 4; q++) {
            int idx4 = q * 256 + tid;
            int row = idx4 >> 4;
            int c4  = idx4 & 15;
            int kk = c * 64 + row;
            float4 v = (kk < N_) ? *(const float4*)(qkv + qkv_base + (size_t)kk * QKVD + 1536 + h * 64 + c4 * 4) : zero4;
            uint4 u; u.x = f2tf(v.x); u.y = f2tf(v.y); u.z = f2tf(v.z); u.w = f2tf(v.w);
            *(uint4*)&s_kv[row * SV_STR + c4 * 4] = u;
        }
        __syncthreads();

        const int qrow = warpM * 16 + groupID;
        #pragma unroll
        for (int kg = 0; kg < 8; kg++) {
            unsigned ap[4];
            int kc = c * 64 + kg * 8 + tid4;
            ap[0] = s_scu[qrow * SC_STR + kc];
            ap[1] = s_scu[(qrow + 8) * SC_STR + kc];
            ap[2] = s_scu[qrow * SC_STR + kc + 4];
            ap[3] = s_scu[(qrow + 8) * SC_STR + kc + 4];
            #pragma unroll
            for (int j = 0; j < 2; j++) {
                int vcol = warpN * 16 + j * 8 + groupID;
                unsigned bv[2];
                bv[0] = s_kv[(kg * 8 + tid4) * SV_STR + vcol];
                bv[1] = s_kv[(kg * 8 + tid4 + 4) * SV_STR + vcol];
                mma8(oacc[j], ap, bv);
            }
        }
    }

    // epilogue: normalize and store
    {
        int r = warpM * 16 + groupID;
        float inv0 = s_inv[r], inv1 = s_inv[r + 8];
        int n0 = q0 + r, n1 = q0 + r + 8;
        #pragma unroll
        for (int j = 0; j < 2; j++) {
            int col = warpN * 16 + j * 8 + tid4 * 2;
            if (n0 < N_) {
                float2 o; o.x = oacc[j][0] * inv0; o.y = oacc[j][1] * inv0;
                *(float2*)&out[((size_t)b * N_ + n0) * DIM_ + h * 64 + col] = o;
            }
            if (n1 < N_) {
                float2 o; o.x = oacc[j][2] * inv1; o.y = oacc[j][3] * inv1;
                *(float2*)&out[((size_t)b * N_ + n1) * DIM_ + h * 64 + col] = o;
            }
        }
    }
}

// ---------------- launch ----------------
extern "C" void kernel_launch(void* const* d_in, const int* in_sizes, int n_in,
                              void* d_out, int out_size)
{
    const float* x     = (const float*)d_in[0];
    const float* n1g   = (const float*)d_in[1];
    const float* n1b   = (const float*)d_in[2];
    const float* qkvw  = (const float*)d_in[3];
    const float* qb    = (const float*)d_in[4];
    const float* vb    = (const float*)d_in[5];
    const float* rpbt  = (const float*)d_in[6];
    const float* projw = (const float*)d_in[7];
    const float* projb = (const float*)d_in[8];
    const float* n2g   = (const float*)d_in[9];
    const float* n2b   = (const float*)d_in[10];
    const float* fc1w  = (const float*)d_in[11];
    const float* fc1b  = (const float*)d_in[12];
    const float* fc2w  = (const float*)d_in[13];
    const float* fc2b  = (const float*)d_in[14];
    const int*   ridx  = (const int*)d_in[15];
    float* out = (float*)d_out;

    float *ph, *pqkv, *patt, *pm, *prpb;
    cudaGetSymbolAddress((void**)&ph,   g_h);
    cudaGetSymbolAddress((void**)&pqkv, g_qkv);
    cudaGetSymbolAddress((void**)&patt, g_att);
    cudaGetSymbolAddress((void**)&pm,   g_m);
    cudaGetSymbolAddress((void**)&prpb, g_rpbf);

    cudaFuncSetAttribute(attn_kernel, cudaFuncAttributeMaxDynamicSharedMemorySize, ATTN_SMEM);

    const int mTiles = (MTOK + 127) / 128;

    ln_kernel<<<MTOK, 256>>>(x, n1g, n1b, ph);
    rpb_expand<<<(NH_ * N_ * N_ + 255) / 256, 256>>>(rpbt, ridx, prpb);
    gemm_tc<1><<<dim3(QKVD / 128, mTiles), 256>>>(ph, qkvw, pqkv, MTOK, QKVD, DIM_, qb, vb, nullptr);
    attn_kernel<<<dim3((N_ + 31) / 32, NH_, B_), 256, ATTN_SMEM>>>(pqkv, prpb, patt);
    gemm_tc<3><<<dim3(DIM_ / 128, mTiles), 256>>>(patt, projw, out, MTOK, DIM_, DIM_, projb, nullptr, x);
    ln_kernel<<<MTOK, 256>>>(out, n2g, n2b, ph);
    gemm_tc<2><<<dim3(MLP_ / 128, mTiles), 256>>>(ph, fc1w, pm, MTOK, MLP_, DIM_, fc1b, nullptr, nullptr);
    gemm_tc<3><<<dim3(DIM_ / 128, mTiles), 256>>>(pm, fc2w, out, MTOK, DIM_, MLP_, fc2b, nullptr, out);
}

// round 4
// speedup vs baseline: 2.9528x; 1.0014x over previous
#include <cuda_runtime.h>
#include <math.h>

#define B_    32
#define N_    577
#define DIM_  768
#define NH_   12
#define HD_   64
#define MLP_  3072
#define MTOK  (B_*N_)          /* 18464 */
#define QKVD  (3*DIM_)         /* 2304 */
#define SCALE_ 0.125f

// attention smem strides (floats) — chosen for conflict-free mma fragment loads
#define SQ_STR 68
#define SK_STR 76
#define SV_STR 72
#define SC_STR 652
#define ATTN_SMEM ((32*SQ_STR + 64*SK_STR + 32*SC_STR + 32) * 4)

// ---------------- scratch ----------------
__device__ float g_h   [(size_t)MTOK * DIM_];
__device__ float g_qkv [(size_t)MTOK * QKVD];
__device__ float g_att [(size_t)MTOK * DIM_];
__device__ float g_m   [(size_t)MTOK * MLP_];
__device__ float g_rpbf[(size_t)NH_ * N_ * N_];

// ---------------- helpers ----------------
__device__ __forceinline__ unsigned f2tf(float f) {
    unsigned u; asm("cvt.rna.tf32.f32 %0, %1;" : "=r"(u) : "f"(f)); return u;
}
__device__ __forceinline__ void mma8(float* c, const unsigned* a, const unsigned* b) {
    asm volatile(
        "mma.sync.aligned.m16n8k8.row.col.f32.tf32.tf32.f32 "
        "{%0,%1,%2,%3},{%4,%5,%6,%7},{%8,%9},{%0,%1,%2,%3};"
        : "+f"(c[0]), "+f"(c[1]), "+f"(c[2]), "+f"(c[3])
        : "r"(a[0]), "r"(a[1]), "r"(a[2]), "r"(a[3]), "r"(b[0]), "r"(b[1]));
}

// ---------------- LayerNorm ----------------
__global__ void __launch_bounds__(256)
ln_kernel(const float* __restrict__ in, const float* __restrict__ g,
          const float* __restrict__ bta, float* __restrict__ out)
{
    __shared__ float red[16];
    __shared__ float s_stats[2];
    const int row = blockIdx.x;
    const int tid = threadIdx.x;
    const float* p = in + (size_t)row * DIM_;
    float v0 = p[tid], v1 = p[tid + 256], v2 = p[tid + 512];
    float s1 = v0 + v1 + v2;
    float s2 = v0*v0 + v1*v1 + v2*v2;
    #pragma unroll
    for (int o = 16; o > 0; o >>= 1) {
        s1 += __shfl_xor_sync(0xffffffffu, s1, o);
        s2 += __shfl_xor_sync(0xffffffffu, s2, o);
    }
    const int warp = tid >> 5, lane = tid & 31;
    if (lane == 0) { red[warp] = s1; red[warp + 8] = s2; }
    __syncthreads();
    if (tid == 0) {
        float t1 = 0.f, t2 = 0.f;
        #pragma unroll
        for (int w = 0; w < 8; w++) { t1 += red[w]; t2 += red[w + 8]; }
        float mean = t1 * (1.f / DIM_);
        float var  = t2 * (1.f / DIM_) - mean * mean;
        s_stats[0] = mean;
        s_stats[1] = rsqrtf(var + 1e-6f);
    }
    __syncthreads();
    const float mean = s_stats[0], inv = s_stats[1];
    float* o = out + (size_t)row * DIM_;
    o[tid]       = (v0 - mean) * inv * g[tid]       + bta[tid];
    o[tid + 256] = (v1 - mean) * inv * g[tid + 256] + bta[tid + 256];
    o[tid + 512] = (v2 - mean) * inv * g[tid + 512] + bta[tid + 512];
}

// ---------------- rel-pos bias expand ----------------
__global__ void rpb_expand(const float* __restrict__ table, const int* __restrict__ relidx,
                           float* __restrict__ out)
{
    int t = blockIdx.x * 256 + threadIdx.x;
    const int total = NH_ * N_ * N_;
    if (t >= total) return;
    int h = t / (N_ * N_);
    int r = t - h * (N_ * N_);
    out[t] = table[relidx[r] * NH_ + h];
}

// ---------------- TF32 tensor-core GEMM NT ----------------
// C[M,Nn] = A[M,K] @ Bw[Nn,K]^T + epilogue
// EPI 1: qkv concat bias   2: gelu(v+bias)   3: res + v + bias
template<int EPI>
__global__ void __launch_bounds__(256)
gemm_tc(const float* __restrict__ A, const float* __restrict__ Bw,
        float* __restrict__ C, int M, int Nn, int K,
        const float* __restrict__ bias, const float* __restrict__ bias2,
        const float* __restrict__ res)
{
    __shared__ unsigned As[128 * 20];
    __shared__ unsigned Bs[128 * 20];
    const int tid = threadIdx.x;
    const int warp = tid >> 5, lane = tid & 31;
    const int groupID = lane >> 2, tid4 = lane & 3;
    const int warpM = warp & 1, warpN = warp >> 1;
    const int mBase = blockIdx.y * 128;
    const int nBase = blockIdx.x * 128;

    // global load mapping: 64 rows per pass, 4 float4 per row
    const int lr  = tid >> 2;       // 0..63
    const int lc4 = tid & 3;        // 0..3

    const bool av0ok = (mBase + lr)      < M;
    const bool av1ok = (mBase + lr + 64) < M;
    const float* Ap0 = A  + (size_t)(mBase + lr)      * K + lc4 * 4;
    const float* Ap1 = A  + (size_t)(mBase + lr + 64) * K + lc4 * 4;
    const float* Bp0 = Bw + (size_t)(nBase + lr)      * K + lc4 * 4;
    const float* Bp1 = Bw + (size_t)(nBase + lr + 64) * K + lc4 * 4;

    float acc[4][4][4];
    #pragma unroll
    for (int i = 0; i < 4; i++)
        #pragma unroll
        for (int j = 0; j < 4; j++)
            #pragma unroll
            for (int r = 0; r < 4; r++) acc[i][j][r] = 0.f;

    const float4 zero4 = make_float4(0.f, 0.f, 0.f, 0.f);
    float4 a0 = av0ok ? *(const float4*)Ap0 : zero4;
    float4 a1 = av1ok ? *(const float4*)Ap1 : zero4;
    float4 b0 = *(const float4*)Bp0;
    float4 b1 = *(const float4*)Bp1;

    for (int k0 = 0; k0 < K; k0 += 16) {
        __syncthreads();
        {
            uint4 u;
            u.x = f2tf(a0.x); u.y = f2tf(a0.y); u.z = f2tf(a0.z); u.w = f2tf(a0.w);
            *(uint4*)&As[lr * 20 + lc4 * 4] = u;
            u.x = f2tf(a1.x); u.y = f2tf(a1.y); u.z = f2tf(a1.z); u.w = f2tf(a1.w);
            *(uint4*)&As[(lr + 64) * 20 + lc4 * 4] = u;
            u.x = f2tf(b0.x); u.y = f2tf(b0.y); u.z = f2tf(b0.z); u.w = f2tf(b0.w);
            *(uint4*)&Bs[lr * 20 + lc4 * 4] = u;
            u.x = f2tf(b1.x); u.y = f2tf(b1.y); u.z = f2tf(b1.z); u.w = f2tf(b1.w);
            *(uint4*)&Bs[(lr + 64) * 20 + lc4 * 4] = u;
        }
        __syncthreads();
        if (k0 + 16 < K) {
            Ap0 += 16; Ap1 += 16; Bp0 += 16; Bp1 += 16;
            a0 = av0ok ? *(const float4*)Ap0 : zero4;
            a1 = av1ok ? *(const float4*)Ap1 : zero4;
            b0 = *(const float4*)Bp0;
            b1 = *(const float4*)Bp1;
        }
        #pragma unroll
        for (int kg = 0; kg < 16; kg += 8) {
            unsigned afr[4][4], bfr[4][2];
            #pragma unroll
            for (int i = 0; i < 4; i++) {
                int r = warpM * 64 + i * 16 + groupID;
                afr[i][0] = As[r * 20 + kg + tid4];
                afr[i][1] = As[(r + 8) * 20 + kg + tid4];
                afr[i][2] = As[r * 20 + kg + tid4 + 4];
                afr[i][3] = As[(r + 8) * 20 + kg + tid4 + 4];
            }
            #pragma unroll
            for (int j = 0; j < 4; j++) {
                int cn = warpN * 32 + j * 8 + groupID;
                bfr[j][0] = Bs[cn * 20 + kg + tid4];
                bfr[j][1] = Bs[cn * 20 + kg + tid4 + 4];
            }
            #pragma unroll
            for (int i = 0; i < 4; i++)
                #pragma unroll
                for (int j = 0; j < 4; j++)
                    mma8(acc[i][j], afr[i], bfr[j]);
        }
    }

    // epilogue
    #pragma unroll
    for (int i = 0; i < 4; i++) {
        int r0 = mBase + warpM * 64 + i * 16 + groupID;
        int r1 = r0 + 8;
        #pragma unroll
        for (int j = 0; j < 4; j++) {
            int cn = nBase + warpN * 32 + j * 8 + tid4 * 2;
            float bv0, bv1;
            if (EPI == 1) {
                bv0 = (cn < 768) ? bias[cn] : ((cn < 1536) ? 0.f : bias2[cn - 1536]);
                int c1 = cn + 1;
                bv1 = (c1 < 768) ? bias[c1] : ((c1 < 1536) ? 0.f : bias2[c1 - 1536]);
            } else {
                bv0 = bias[cn]; bv1 = bias[cn + 1];
            }
            #pragma unroll
            for (int rr = 0; rr < 2; rr++) {
                int gm = rr ? r1 : r0;
                if (gm >= M) continue;
                size_t off = (size_t)gm * Nn + cn;
                float v0 = acc[i][j][rr * 2 + 0] + bv0;
                float v1 = acc[i][j][rr * 2 + 1] + bv1;
                if (EPI == 2) {
                    v0 = 0.5f * v0 * (1.f + erff(v0 * 0.70710678118654752f));
                    v1 = 0.5f * v1 * (1.f + erff(v1 * 0.70710678118654752f));
                } else if (EPI == 3) {
                    v0 += res[off]; v1 += res[off + 1];
                }
                float2 o; o.x = v0; o.y = v1;
                *(float2*)&C[off] = o;
            }
        }
    }
}

// ---------------- fused tensor-core attention ----------------
__global__ void __launch_bounds__(256)
attn_kernel(const float* __restrict__ qkv, const float* __restrict__ rpbf,
            float* __restrict__ out)
{
    extern __shared__ unsigned smu[];
    unsigned* s_q  = smu;                       // 32*68
    unsigned* s_kv = smu + 32 * SQ_STR;         // 64*76 (K) / 64*72 (V)
    float*    s_sc = (float*)(s_kv + 64 * SK_STR); // 32*652
    float*    s_inv = s_sc + 32 * SC_STR;       // 32

    const int tid = threadIdx.x;
    const int warp = tid >> 5, lane = tid & 31;
    const int groupID = lane >> 2, tid4 = lane & 3;
    const int warpM = warp & 1, warpN = warp >> 1;
    const int q0 = blockIdx.x * 32;
    const int h  = blockIdx.y;
    const int b  = blockIdx.z;
    const size_t qkv_base = (size_t)b * N_ * QKVD;
    const float4 zero4 = make_float4(0.f, 0.f, 0.f, 0.f);

    // load Q tile (pre-scaled, tf32)
    #pragma unroll
    for (int q = 0; q < 2; q++) {
        int idx4 = q * 256 + tid;
        int row = idx4 >> 4;
        int c4  = idx4 & 15;
        int n = q0 + row;
        float4 v = (n < N_) ? *(const float4*)(qkv + qkv_base + (size_t)n * QKVD + h * 64 + c4 * 4) : zero4;
        uint4 u;
        u.x = f2tf(v.x * SCALE_); u.y = f2tf(v.y * SCALE_);
        u.z = f2tf(v.z * SCALE_); u.w = f2tf(v.w * SCALE_);
        *(uint4*)&s_q[row * SQ_STR + c4 * 4] = u;
    }

    // ---- S = (Q*scale) K^T ----
    for (int c = 0; c < 10; c++) {
        __syncthreads();
        #pragma unroll
        for (int q = 0; q < 4; q++) {
            int idx4 = q * 256 + tid;
            int row = idx4 >> 4;
            int c4  = idx4 & 15;
            int kk = c * 64 + row;
            float4 v = (kk < N_) ? *(const float4*)(qkv + qkv_base + (size_t)kk * QKVD + 768 + h * 64 + c4 * 4) : zero4;
            uint4 u; u.x = f2tf(v.x); u.y = f2tf(v.y); u.z = f2tf(v.z); u.w = f2tf(v.w);
            *(uint4*)&s_kv[row * SK_STR + c4 * 4] = u;
        }
        __syncthreads();

        float sacc[2][4];
        #pragma unroll
        for (int j = 0; j < 2; j++)
            #pragma unroll
            for (int r = 0; r < 4; r++) sacc[j][r] = 0.f;
        const int qrow = warpM * 16 + groupID;
        #pragma unroll
        for (int kg = 0; kg < 8; kg++) {
            unsigned aq[4];
            aq[0] = s_q[qrow * SQ_STR + kg * 8 + tid4];
            aq[1] = s_q[(qrow + 8) * SQ_STR + kg * 8 + tid4];
            aq[2] = s_q[qrow * SQ_STR + kg * 8 + tid4 + 4];
            aq[3] = s_q[(qrow + 8) * SQ_STR + kg * 8 + tid4 + 4];
            #pragma unroll
            for (int j = 0; j < 2; j++) {
                int kcol = warpN * 16 + j * 8 + groupID;
                unsigned bk[2];
                bk[0] = s_kv[kcol * SK_STR + kg * 8 + tid4];
                bk[1] = s_kv[kcol * SK_STR + kg * 8 + tid4 + 4];
                mma8(sacc[j], aq, bk);
            }
        }
        #pragma unroll
        for (int j = 0; j < 2; j++) {
            int col = c * 64 + warpN * 16 + j * 8 + tid4 * 2;
            int r = warpM * 16 + groupID;
            s_sc[r * SC_STR + col]           = (col     < N_) ? sacc[j][0] : 0.f;
            s_sc[r * SC_STR + col + 1]       = (col + 1 < N_) ? sacc[j][1] : 0.f;
            s_sc[(r + 8) * SC_STR + col]     = (col     < N_) ? sacc[j][2] : 0.f;
            s_sc[(r + 8) * SC_STR + col + 1] = (col + 1 < N_) ? sacc[j][3] : 0.f;
        }
    }
    __syncthreads();

    // ---- softmax (+rpb); store unnormalized exp as tf32, keep 1/sum ----
    {
        for (int row = warp; row < 32; row += 8) {
            int nrow = q0 + row;
            const float* rb = rpbf + ((size_t)h * N_ + (nrow < N_ ? nrow : 0)) * N_;
            float* sr = s_sc + row * SC_STR;
            float mx = -1e30f;
            for (int j = lane; j < N_; j += 32) mx = fmaxf(mx, sr[j] + rb[j]);
            #pragma unroll
            for (int o = 16; o > 0; o >>= 1) mx = fmaxf(mx, __shfl_xor_sync(0xffffffffu, mx, o));
            float sum = 0.f;
            for (int j = lane; j < N_; j += 32) {
                float e = __expf(sr[j] + rb[j] - mx);
                sr[j] = __uint_as_float(f2tf(e));
                sum += e;
            }
            #pragma unroll
            for (int o = 16; o > 0; o >>= 1) sum += __shfl_xor_sync(0xffffffffu, sum, o);
            if (lane == 0) s_inv[row] = 1.f / sum;
        }
    }

    // ---- O = P @ V ----
    float oacc[2][4];
    #pragma unroll
    for (int j = 0; j < 2; j++)
        #pragma unroll
        for (int r = 0; r < 4; r++) oacc[j][r] = 0.f;

    const unsigned* s_scu = (const unsigned*)s_sc;
    for (int c = 0; c < 10; c++) {
        __syncthreads();
        #pragma unroll
        for (int q = 0; q < 4; q++) {
            int idx4 = q * 256 + tid;
            int row = idx4 >> 4;
            int c4  = idx4 & 15;
            int kk = c * 64 + row;
            float4 v = (kk < N_) ? *(const float4*)(qkv + qkv_base + (size_t)kk * QKVD + 1536 + h * 64 + c4 * 4) : zero4;
            uint4 u; u.x = f2tf(v.x); u.y = f2tf(v.y); u.z = f2tf(v.z); u.w = f2tf(v.w);
            *(uint4*)&s_kv[row * SV_STR + c4 * 4] = u;
        }
        __syncthreads();

        const int qrow = warpM * 16 + groupID;
        #pragma unroll
        for (int kg = 0; kg < 8; kg++) {
            unsigned ap[4];
            int kc = c * 64 + kg * 8 + tid4;
            ap[0] = s_scu[qrow * SC_STR + kc];
            ap[1] = s_scu[(qrow + 8) * SC_STR + kc];
            ap[2] = s_scu[qrow * SC_STR + kc + 4];
            ap[3] = s_scu[(qrow + 8) * SC_STR + kc + 4];
            #pragma unroll
            for (int j = 0; j < 2; j++) {
                int vcol = warpN * 16 + j * 8 + groupID;
                unsigned bv[2];
                bv[0] = s_kv[(kg * 8 + tid4) * SV_STR + vcol];
                bv[1] = s_kv[(kg * 8 + tid4 + 4) * SV_STR + vcol];
                mma8(oacc[j], ap, bv);
            }
        }
    }

    // epilogue: normalize and store
    {
        int r = warpM * 16 + groupID;
        float inv0 = s_inv[r], inv1 = s_inv[r + 8];
        int n0 = q0 + r, n1 = q0 + r + 8;
        #pragma unroll
        for (int j = 0; j < 2; j++) {
            int col = warpN * 16 + j * 8 + tid4 * 2;
            if (n0 < N_) {
                float2 o; o.x = oacc[j][0] * inv0; o.y = oacc[j][1] * inv0;
                *(float2*)&out[((size_t)b * N_ + n0) * DIM_ + h * 64 + col] = o;
            }
            if (n1 < N_) {
                float2 o; o.x = oacc[j][2] * inv1; o.y = oacc[j][3] * inv1;
                *(float2*)&out[((size_t)b * N_ + n1) * DIM_ + h * 64 + col] = o;
            }
        }
    }
}

// ---------------- launch ----------------
extern "C" void kernel_launch(void* const* d_in, const int* in_sizes, int n_in,
                              void* d_out, int out_size)
{
    const float* x     = (const float*)d_in[0];
    const float* n1g   = (const float*)d_in[1];
    const float* n1b   = (const float*)d_in[2];
    const float* qkvw  = (const float*)d_in[3];
    const float* qb    = (const float*)d_in[4];
    const float* vb    = (const float*)d_in[5];
    const float* rpbt  = (const float*)d_in[6];
    const float* projw = (const float*)d_in[7];
    const float* projb = (const float*)d_in[8];
    const float* n2g   = (const float*)d_in[9];
    const float* n2b   = (const float*)d_in[10];
    const float* fc1w  = (const float*)d_in[11];
    const float* fc1b  = (const float*)d_in[12];
    const float* fc2w  = (const float*)d_in[13];
    const float* fc2b  = (const float*)d_in[14];
    const int*   ridx  = (const int*)d_in[15];
    float* out = (float*)d_out;

    float *ph, *pqkv, *patt, *pm, *prpb;
    cudaGetSymbolAddress((void**)&ph,   g_h);
    cudaGetSymbolAddress((void**)&pqkv, g_qkv);
    cudaGetSymbolAddress((void**)&patt, g_att);
    cudaGetSymbolAddress((void**)&pm,   g_m);
    cudaGetSymbolAddress((void**)&prpb, g_rpbf);

    cudaFuncSetAttribute(attn_kernel, cudaFuncAttributeMaxDynamicSharedMemorySize, ATTN_SMEM);

    const int mTiles = (MTOK + 127) / 128;

    ln_kernel<<<MTOK, 256>>>(x, n1g, n1b, ph);
    rpb_expand<<<(NH_ * N_ * N_ + 255) / 256, 256>>>(rpbt, ridx, prpb);
    gemm_tc<1><<<dim3(QKVD / 128, mTiles), 256>>>(ph, qkvw, pqkv, MTOK, QKVD, DIM_, qb, vb, nullptr);
    attn_kernel<<<dim3((N_ + 31) / 32, NH_, B_), 256, ATTN_SMEM>>>(pqkv, prpb, patt);
    gemm_tc<3><<<dim3(DIM_ / 128, mTiles), 256>>>(patt, projw, out, MTOK, DIM_, DIM_, projb, nullptr, x);
    ln_kernel<<<MTOK, 256>>>(out, n2g, n2b, ph);
    gemm_tc<2><<<dim3(MLP_ / 128, mTiles), 256>>>(ph, fc1w, pm, MTOK, MLP_, DIM_, fc1b, nullptr, nullptr);
    gemm_tc<3><<<dim3(DIM_ / 128, mTiles), 256>>>(pm, fc2w, out, MTOK, DIM_, MLP_, fc2b, nullptr, out);
}

// round 5
// speedup vs baseline: 3.7920x; 1.2842x over previous
#include <cuda_runtime.h>
#include <math.h>

#define B_    32
#define N_    577
#define DIM_  768
#define NH_   12
#define HD_   64
#define MLP_  3072
#define MTOK  (B_*N_)          /* 18464 */
#define QKVD  (3*DIM_)         /* 2304 */
#define SCALE_ 0.125f

// ---------------- scratch ----------------
__device__ float g_h   [(size_t)MTOK * DIM_];
__device__ float g_qkv [(size_t)MTOK * QKVD];
__device__ float g_att [(size_t)MTOK * DIM_];
__device__ float g_m   [(size_t)MTOK * MLP_];
__device__ float g_rpbf[(size_t)NH_ * N_ * N_];

// ---------------- helpers ----------------
__device__ __forceinline__ void cp16(void* dst, const void* src, bool valid) {
    unsigned d = (unsigned)__cvta_generic_to_shared(dst);
    int sz = valid ? 16 : 0;
    asm volatile("cp.async.cg.shared.global [%0], [%1], 16, %2;\n" :: "r"(d), "l"(src), "r"(sz));
}
__device__ __forceinline__ void cp_commit() { asm volatile("cp.async.commit_group;\n"); }
template<int Nw> __device__ __forceinline__ void cp_wait() {
    asm volatile("cp.async.wait_group %0;\n" :: "n"(Nw));
}
__device__ __forceinline__ void mma8(float* c, const unsigned* a, const unsigned* b) {
    asm volatile(
        "mma.sync.aligned.m16n8k8.row.col.f32.tf32.tf32.f32 "
        "{%0,%1,%2,%3},{%4,%5,%6,%7},{%8,%9},{%0,%1,%2,%3};"
        : "+f"(c[0]), "+f"(c[1]), "+f"(c[2]), "+f"(c[3])
        : "r"(a[0]), "r"(a[1]), "r"(a[2]), "r"(a[3]), "r"(b[0]), "r"(b[1]));
}

// ---------------- LayerNorm ----------------
__global__ void __launch_bounds__(256)
ln_kernel(const float* __restrict__ in, const float* __restrict__ g,
          const float* __restrict__ bta, float* __restrict__ out)
{
    __shared__ float red[16];
    __shared__ float s_stats[2];
    const int row = blockIdx.x;
    const int tid = threadIdx.x;
    const float* p = in + (size_t)row * DIM_;
    float v0 = p[tid], v1 = p[tid + 256], v2 = p[tid + 512];
    float s1 = v0 + v1 + v2;
    float s2 = v0*v0 + v1*v1 + v2*v2;
    #pragma unroll
    for (int o = 16; o > 0; o >>= 1) {
        s1 += __shfl_xor_sync(0xffffffffu, s1, o);
        s2 += __shfl_xor_sync(0xffffffffu, s2, o);
    }
    const int warp = tid >> 5, lane = tid & 31;
    if (lane == 0) { red[warp] = s1; red[warp + 8] = s2; }
    __syncthreads();
    if (tid == 0) {
        float t1 = 0.f, t2 = 0.f;
        #pragma unroll
        for (int w = 0; w < 8; w++) { t1 += red[w]; t2 += red[w + 8]; }
        float mean = t1 * (1.f / DIM_);
        float var  = t2 * (1.f / DIM_) - mean * mean;
        s_stats[0] = mean;
        s_stats[1] = rsqrtf(var + 1e-6f);
    }
    __syncthreads();
    const float mean = s_stats[0], inv = s_stats[1];
    float* o = out + (size_t)row * DIM_;
    o[tid]       = (v0 - mean) * inv * g[tid]       + bta[tid];
    o[tid + 256] = (v1 - mean) * inv * g[tid + 256] + bta[tid + 256];
    o[tid + 512] = (v2 - mean) * inv * g[tid + 512] + bta[tid + 512];
}

// ---------------- rel-pos bias expand ----------------
__global__ void rpb_expand(const float* __restrict__ table, const int* __restrict__ relidx,
                           float* __restrict__ out)
{
    int t = blockIdx.x * 256 + threadIdx.x;
    const int total = NH_ * N_ * N_;
    if (t >= total) return;
    int h = t / (N_ * N_);
    int r = t - h * (N_ * N_);
    out[t] = table[relidx[r] * NH_ + h];
}

// ---------------- TF32 tensor-core GEMM NT with cp.async 3-stage pipeline ----------------
// C[M,Nn] = A[M,K] @ Bw[Nn,K]^T + epilogue
// EPI 1: qkv concat bias   2: gelu(v+bias)   3: res + v + bias
#define GST 2560  /* floats per stage per matrix = 128*20 */
#define GEMM_SMEM (3 * GST * 2 * 4)

template<int EPI>
__global__ void __launch_bounds__(256, 2)
gemm_tc(const float* __restrict__ A, const float* __restrict__ Bw,
        float* __restrict__ C, int M, int Nn, int K,
        const float* __restrict__ bias, const float* __restrict__ bias2,
        const float* __restrict__ res)
{
    extern __shared__ float sm[];
    float* As = sm;             // [3][128*20]
    float* Bs = sm + 3 * GST;   // [3][128*20]

    const int tid = threadIdx.x;
    const int warp = tid >> 5, lane = tid & 31;
    const int groupID = lane >> 2, tid4 = lane & 3;
    const int warpM = warp & 1, warpN = warp >> 1;
    const int mBase = blockIdx.y * 128;
    const int nBase = blockIdx.x * 128;

    const int lr = tid >> 1;         // 0..127
    const int c0 = (tid & 1) * 8;    // 0 or 8

    const bool avok = (mBase + lr) < M;
    const float* Ap = A  + (size_t)(mBase + lr) * K + c0;
    const float* Bp = Bw + (size_t)(nBase + lr) * K + c0;

    float acc[4][4][4];
    #pragma unroll
    for (int i = 0; i < 4; i++)
        #pragma unroll
        for (int j = 0; j < 4; j++)
            #pragma unroll
            for (int r = 0; r < 4; r++) acc[i][j][r] = 0.f;

    const int nk = K >> 4;

    // issue loads for stage s covering k-slice ks*16
    auto issue = [&](int s, int ks) {
        float* ad = &As[s * GST + lr * 20 + c0];
        float* bd = &Bs[s * GST + lr * 20 + c0];
        const float* ap = Ap + ks * 16;
        const float* bp = Bp + ks * 16;
        cp16(ad,     avok ? ap     : A, avok);
        cp16(ad + 4, avok ? ap + 4 : A, avok);
        cp16(bd,     bp,     true);
        cp16(bd + 4, bp + 4, true);
    };

    issue(0, 0); cp_commit();
    issue(1, 1); cp_commit();

    for (int i = 0; i < nk; i++) {
        cp_wait<1>();
        __syncthreads();
        if (i + 2 < nk) issue((i + 2) % 3, i + 2);
        cp_commit();

        const unsigned* as = (const unsigned*)&As[(i % 3) * GST];
        const unsigned* bs = (const unsigned*)&Bs[(i % 3) * GST];
        #pragma unroll
        for (int kg = 0; kg < 16; kg += 8) {
            unsigned afr[4][4], bfr[4][2];
            #pragma unroll
            for (int ii = 0; ii < 4; ii++) {
                int r = warpM * 64 + ii * 16 + groupID;
                afr[ii][0] = as[r * 20 + kg + tid4];
                afr[ii][1] = as[(r + 8) * 20 + kg + tid4];
                afr[ii][2] = as[r * 20 + kg + tid4 + 4];
                afr[ii][3] = as[(r + 8) * 20 + kg + tid4 + 4];
            }
            #pragma unroll
            for (int j = 0; j < 4; j++) {
                int cn = warpN * 32 + j * 8 + groupID;
                bfr[j][0] = bs[cn * 20 + kg + tid4];
                bfr[j][1] = bs[cn * 20 + kg + tid4 + 4];
            }
            #pragma unroll
            for (int ii = 0; ii < 4; ii++)
                #pragma unroll
                for (int j = 0; j < 4; j++)
                    mma8(acc[ii][j], afr[ii], bfr[j]);
        }
        __syncthreads();
    }

    // epilogue
    #pragma unroll
    for (int i = 0; i < 4; i++) {
        int r0 = mBase + warpM * 64 + i * 16 + groupID;
        int r1 = r0 + 8;
        #pragma unroll
        for (int j = 0; j < 4; j++) {
            int cn = nBase + warpN * 32 + j * 8 + tid4 * 2;
            float bv0, bv1;
            if (EPI == 1) {
                bv0 = (cn < 768) ? bias[cn] : ((cn < 1536) ? 0.f : bias2[cn - 1536]);
                int c1 = cn + 1;
                bv1 = (c1 < 768) ? bias[c1] : ((c1 < 1536) ? 0.f : bias2[c1 - 1536]);
            } else {
                bv0 = bias[cn]; bv1 = bias[cn + 1];
            }
            #pragma unroll
            for (int rr = 0; rr < 2; rr++) {
                int gm = rr ? r1 : r0;
                if (gm >= M) continue;
                size_t off = (size_t)gm * Nn + cn;
                float v0 = acc[i][j][rr * 2 + 0] + bv0;
                float v1 = acc[i][j][rr * 2 + 1] + bv1;
                if (EPI == 2) {
                    v0 = 0.5f * v0 * (1.f + erff(v0 * 0.70710678118654752f));
                    v1 = 0.5f * v1 * (1.f + erff(v1 * 0.70710678118654752f));
                } else if (EPI == 3) {
                    v0 += res[off]; v1 += res[off + 1];
                }
                float2 o; o.x = v0; o.y = v1;
                *(float2*)&C[off] = o;
            }
        }
    }
}

// ---------------- flash attention: 128 queries/block, online softmax ----------------
#define KSTR 68
#define VSTR 72
#define PSTR 68
#define NCH  10     /* ceil(577/64) */
#define SKV_F (64*KSTR + 64*VSTR)                 /* floats per KV stage */
#define ATTN_SMEM ((2*SKV_F + 128*PSTR) * 4)      /* 106496 bytes */

__global__ void __launch_bounds__(256, 2)
attn_kernel(const float* __restrict__ qkv, const float* __restrict__ rpbf,
            float* __restrict__ out)
{
    extern __shared__ float sm[];
    float* sK0 = sm;                       // stage 0: K then V
    float* sV0 = sm + 64 * KSTR;
    float* sK1 = sm + SKV_F;               // stage 1
    float* sV1 = sK1 + 64 * KSTR;
    float* sP  = sm + 2 * SKV_F;           // 128*PSTR (also Q staging)

    const int tid = threadIdx.x;
    const int warp = tid >> 5, lane = tid & 31;
    const int groupID = lane >> 2, tid4 = lane & 3;
    const int q0 = blockIdx.x * 128;
    const int h  = blockIdx.y;
    const int b  = blockIdx.z;
    const size_t qkv_base = (size_t)b * N_ * QKVD + h * 64;

    // ---- Q load into sP via cp.async (8 float4 per thread) ----
    {
        const float* qsrc = qkv + qkv_base;
        #pragma unroll
        for (int p = 0; p < 8; p++) {
            int f4 = p * 256 + tid;          // 0..2047
            int row = f4 >> 4;               // 0..127
            int cc = (f4 & 15) * 4;
            int n = q0 + row;
            bool v = n < N_;
            cp16(&sP[row * PSTR + cc], v ? (qsrc + (size_t)n * QKVD + cc) : qkv, v);
        }
        cp_commit();
    }

    // ---- KV chunk loader ----
    auto issueKV = [&](int c) {
        float* kD = (c & 1) ? sK1 : sK0;
        float* vD = (c & 1) ? sV1 : sV0;
        const float* ks = qkv + qkv_base + 768;
        const float* vs = qkv + qkv_base + 1536;
        #pragma unroll
        for (int p = 0; p < 4; p++) {
            int f4 = p * 256 + tid;          // 0..1023
            int row = f4 >> 4;               // 0..63
            int cc = (f4 & 15) * 4;
            int kk = c * 64 + row;
            bool v = kk < N_;
            cp16(&kD[row * KSTR + cc], v ? (ks + (size_t)kk * QKVD + cc) : qkv, v);
            cp16(&vD[row * VSTR + cc], v ? (vs + (size_t)kk * QKVD + cc) : qkv, v);
        }
        cp_commit();
    };

    issueKV(0);
    issueKV(1);

    // ---- wait Q, read Q fragments into registers ----
    cp_wait<2>();
    __syncthreads();
    unsigned aq[8][4];
    {
        const unsigned* sPu = (const unsigned*)sP;
        int r = warp * 16 + groupID;
        #pragma unroll
        for (int kg = 0; kg < 8; kg++) {
            aq[kg][0] = sPu[r * PSTR + kg * 8 + tid4];
            aq[kg][1] = sPu[(r + 8) * PSTR + kg * 8 + tid4];
            aq[kg][2] = sPu[r * PSTR + kg * 8 + tid4 + 4];
            aq[kg][3] = sPu[(r + 8) * PSTR + kg * 8 + tid4 + 4];
        }
    }
    __syncthreads();   // everyone has Q frags; sP free for P

    const int n0 = q0 + warp * 16 + groupID;
    const int n1 = n0 + 8;
    const float* rpb0 = rpbf + ((size_t)h * N_ + (n0 < N_ ? n0 : 0)) * N_;
    const float* rpb1 = rpbf + ((size_t)h * N_ + (n1 < N_ ? n1 : 0)) * N_;

    float m0 = -1e30f, m1 = -1e30f, l0 = 0.f, l1 = 0.f;
    float oacc[8][4];
    #pragma unroll
    for (int j = 0; j < 8; j++)
        #pragma unroll
        for (int r = 0; r < 4; r++) oacc[j][r] = 0.f;

    for (int c = 0; c < NCH; c++) {
        cp_wait<1>();
        __syncthreads();
        const unsigned* sKu = (const unsigned*)((c & 1) ? sK1 : sK0);
        const unsigned* sVu = (const unsigned*)((c & 1) ? sV1 : sV0);

        // ---- S = Q K^T ----
        float sc[8][4];
        #pragma unroll
        for (int j = 0; j < 8; j++)
            #pragma unroll
            for (int r = 0; r < 4; r++) sc[j][r] = 0.f;
        #pragma unroll
        for (int kg = 0; kg < 8; kg++) {
            #pragma unroll
            for (int j = 0; j < 8; j++) {
                int kcol = j * 8 + groupID;
                unsigned bk[2];
                bk[0] = sKu[kcol * KSTR + kg * 8 + tid4];
                bk[1] = sKu[kcol * KSTR + kg * 8 + tid4 + 4];
                mma8(sc[j], aq[kg], bk);
            }
        }

        // ---- scale + rpb + mask; online softmax ----
        const int cbase = c * 64;
        float mx0 = m0, mx1 = m1;
        #pragma unroll
        for (int j = 0; j < 8; j++) {
            int col = cbase + j * 8 + tid4 * 2;
            bool v0 = col < N_, v1 = (col + 1) < N_;
            sc[j][0] = v0 ? sc[j][0] * SCALE_ + rpb0[col]     : -1e30f;
            sc[j][1] = v1 ? sc[j][1] * SCALE_ + rpb0[col + 1] : -1e30f;
            sc[j][2] = v0 ? sc[j][2] * SCALE_ + rpb1[col]     : -1e30f;
            sc[j][3] = v1 ? sc[j][3] * SCALE_ + rpb1[col + 1] : -1e30f;
            mx0 = fmaxf(mx0, fmaxf(sc[j][0], sc[j][1]));
            mx1 = fmaxf(mx1, fmaxf(sc[j][2], sc[j][3]));
        }
        #pragma unroll
        for (int o = 1; o <= 2; o <<= 1) {
            mx0 = fmaxf(mx0, __shfl_xor_sync(0xffffffffu, mx0, o));
            mx1 = fmaxf(mx1, __shfl_xor_sync(0xffffffffu, mx1, o));
        }
        float f0 = __expf(m0 - mx0), f1 = __expf(m1 - mx1);
        m0 = mx0; m1 = mx1;

        float rs0 = 0.f, rs1 = 0.f;
        {
            int rloc = warp * 16 + groupID;
            #pragma unroll
            for (int j = 0; j < 8; j++) {
                float p00 = __expf(sc[j][0] - m0);
                float p01 = __expf(sc[j][1] - m0);
                float p10 = __expf(sc[j][2] - m1);
                float p11 = __expf(sc[j][3] - m1);
                rs0 += p00 + p01; rs1 += p10 + p11;
                int col = j * 8 + tid4 * 2;
                float2 w0; w0.x = p00; w0.y = p01;
                float2 w1; w1.x = p10; w1.y = p11;
                *(float2*)&sP[rloc * PSTR + col] = w0;
                *(float2*)&sP[(rloc + 8) * PSTR + col] = w1;
            }
        }
        #pragma unroll
        for (int o = 1; o <= 2; o <<= 1) {
            rs0 += __shfl_xor_sync(0xffffffffu, rs0, o);
            rs1 += __shfl_xor_sync(0xffffffffu, rs1, o);
        }
        l0 = l0 * f0 + rs0;
        l1 = l1 * f1 + rs1;
        #pragma unroll
        for (int j = 0; j < 8; j++) {
            oacc[j][0] *= f0; oacc[j][1] *= f0;
            oacc[j][2] *= f1; oacc[j][3] *= f1;
        }
        __syncwarp();

        // ---- O += P V ----
        {
            const unsigned* sPu = (const unsigned*)sP;
            int rloc = warp * 16 + groupID;
            #pragma unroll
            for (int kg = 0; kg < 8; kg++) {
                unsigned ap[4];
                ap[0] = sPu[rloc * PSTR + kg * 8 + tid4];
                ap[1] = sPu[(rloc + 8) * PSTR + kg * 8 + tid4];
                ap[2] = sPu[rloc * PSTR + kg * 8 + tid4 + 4];
                ap[3] = sPu[(rloc + 8) * PSTR + kg * 8 + tid4 + 4];
                #pragma unroll
                for (int j = 0; j < 8; j++) {
                    int vcol = j * 8 + groupID;
                    unsigned bv[2];
                    bv[0] = sVu[(kg * 8 + tid4) * VSTR + vcol];
                    bv[1] = sVu[(kg * 8 + tid4 + 4) * VSTR + vcol];
                    mma8(oacc[j], ap, bv);
                }
            }
        }
        __syncthreads();
        if (c + 2 < NCH) issueKV(c + 2);
        else cp_commit();   // keep group accounting aligned
    }

    // ---- normalize + store ----
    {
        float inv0 = 1.f / l0, inv1 = 1.f / l1;
        #pragma unroll
        for (int j = 0; j < 8; j++) {
            int col = j * 8 + tid4 * 2;
            if (n0 < N_) {
                float2 o; o.x = oacc[j][0] * inv0; o.y = oacc[j][1] * inv0;
                *(float2*)&out[((size_t)b * N_ + n0) * DIM_ + h * 64 + col] = o;
            }
            if (n1 < N_) {
                float2 o; o.x = oacc[j][2] * inv1; o.y = oacc[j][3] * inv1;
                *(float2*)&out[((size_t)b * N_ + n1) * DIM_ + h * 64 + col] = o;
            }
        }
    }
}

// ---------------- launch ----------------
extern "C" void kernel_launch(void* const* d_in, const int* in_sizes, int n_in,
                              void* d_out, int out_size)
{
    const float* x     = (const float*)d_in[0];
    const float* n1g   = (const float*)d_in[1];
    const float* n1b   = (const float*)d_in[2];
    const float* qkvw  = (const float*)d_in[3];
    const float* qb    = (const float*)d_in[4];
    const float* vb    = (const float*)d_in[5];
    const float* rpbt  = (const float*)d_in[6];
    const float* projw = (const float*)d_in[7];
    const float* projb = (const float*)d_in[8];
    const float* n2g   = (const float*)d_in[9];
    const float* n2b   = (const float*)d_in[10];
    const float* fc1w  = (const float*)d_in[11];
    const float* fc1b  = (const float*)d_in[12];
    const float* fc2w  = (const float*)d_in[13];
    const float* fc2b  = (const float*)d_in[14];
    const int*   ridx  = (const int*)d_in[15];
    float* out = (float*)d_out;

    float *ph, *pqkv, *patt, *pm, *prpb;
    cudaGetSymbolAddress((void**)&ph,   g_h);
    cudaGetSymbolAddress((void**)&pqkv, g_qkv);
    cudaGetSymbolAddress((void**)&patt, g_att);
    cudaGetSymbolAddress((void**)&pm,   g_m);
    cudaGetSymbolAddress((void**)&prpb, g_rpbf);

    static bool attr_done = false;
    if (!attr_done) {
        cudaFuncSetAttribute(gemm_tc<1>, cudaFuncAttributeMaxDynamicSharedMemorySize, GEMM_SMEM);
        cudaFuncSetAttribute(gemm_tc<2>, cudaFuncAttributeMaxDynamicSharedMemorySize, GEMM_SMEM);
        cudaFuncSetAttribute(gemm_tc<3>, cudaFuncAttributeMaxDynamicSharedMemorySize, GEMM_SMEM);
        cudaFuncSetAttribute(attn_kernel, cudaFuncAttributeMaxDynamicSharedMemorySize, ATTN_SMEM);
        attr_done = true;
    }

    const int mTiles = (MTOK + 127) / 128;

    ln_kernel<<<MTOK, 256>>>(x, n1g, n1b, ph);
    rpb_expand<<<(NH_ * N_ * N_ + 255) / 256, 256>>>(rpbt, ridx, prpb);
    gemm_tc<1><<<dim3(QKVD / 128, mTiles), 256, GEMM_SMEM>>>(ph, qkvw, pqkv, MTOK, QKVD, DIM_, qb, vb, nullptr);
    attn_kernel<<<dim3((N_ + 127) / 128, NH_, B_), 256, ATTN_SMEM>>>(pqkv, prpb, patt);
    gemm_tc<3><<<dim3(DIM_ / 128, mTiles), 256, GEMM_SMEM>>>(patt, projw, out, MTOK, DIM_, DIM_, projb, nullptr, x);
    ln_kernel<<<MTOK, 256>>>(out, n2g, n2b, ph);
    gemm_tc<2><<<dim3(MLP_ / 128, mTiles), 256, GEMM_SMEM>>>(ph, fc1w, pm, MTOK, MLP_, DIM_, fc1b, nullptr, nullptr);
    gemm_tc<3><<<dim3(DIM_ / 128, mTiles), 256, GEMM_SMEM>>>(pm, fc2w, out, MTOK, DIM_, MLP_, fc2b, nullptr, out);
}